// round 16
// baseline (speedup 1.0000x reference)
#include <cuda_runtime.h>
#include <cuda_bf16.h>
#include <cstdint>

// ============================================================================
// SSIM loss, separable Gaussian, 4-signal (u=x+y, v=x-y), f32x2 packed math.
// R16: h-pass intermediates stored as raw f32x2 (u64) -> no pack/unpack ALU
// in v-pass or h-pass output. plane stays bf16x2 to keep 3 CTAs/SM
// (73.5 KB x 3 = 220.5 KB smem).
// ============================================================================

static constexpr int THREADS = 384;
static constexpr int NBLK    = 2048;
static constexpr float C1 = 1.0e-4f;
static constexpr float C2 = 9.0e-4f;

__device__ constexpr float G[11] = {
    0.00102840f, 0.00759878f, 0.03600077f, 0.10936042f, 0.21300560f,
    0.26601170f,
    0.21300560f, 0.10936042f, 0.03600077f, 0.00759878f, 0.00102840f
};

typedef unsigned long long u64;

struct SmemLayout {
    uint32_t plane[64][67];     // bf16x2 (hi=v, lo=u)            17,152 B
    u64 hpq[64][55];            // f32x2 (lo=p,  hi=q)            28,160 B
    u64 hs [64][55];            // f32x2 (lo=su, hi=sv)           28,160 B
    float red[THREADS / 32];
    unsigned int ticket;
};
static constexpr int SMEM_BYTES = (int)sizeof(SmemLayout);   // ~73.5 KB

__device__ float        g_part[NBLK];
__device__ unsigned int g_count = 0;

__device__ __forceinline__ uint32_t pk(float hi, float lo) {
    uint32_t r;
    asm("cvt.rn.bf16x2.f32 %0, %1, %2;" : "=r"(r) : "f"(hi), "f"(lo));
    return r;
}
// bf16x2 word -> packed f32x2 (lo lane = low bf16, hi lane = high bf16)
__device__ __forceinline__ u64 up2(uint32_t w) {
    u64 r;
    const uint32_t lo = w << 16;
    const uint32_t hi = w & 0xFFFF0000u;
    asm("mov.b64 %0, {%1, %2};" : "=l"(r) : "r"(lo), "r"(hi));
    return r;
}
__device__ __forceinline__ u64 pack2(float lo, float hi) {
    u64 r;
    asm("mov.b64 %0, {%1, %2};" : "=l"(r) : "f"(lo), "f"(hi));
    return r;
}
__device__ __forceinline__ void unpack2(u64 p, float& lo, float& hi) {
    asm("mov.b64 {%0, %1}, %2;" : "=f"(lo), "=f"(hi) : "l"(p));
}
__device__ __forceinline__ u64 fma2(u64 a, u64 b, u64 c) {
    u64 d;
    asm("fma.rn.f32x2 %0, %1, %2, %3;" : "=l"(d) : "l"(a), "l"(b), "l"(c));
    return d;
}
__device__ __forceinline__ u64 mul2(u64 a, u64 b) {
    u64 d;
    asm("mul.rn.f32x2 %0, %1, %2;" : "=l"(d) : "l"(a), "l"(b));
    return d;
}

__global__ __launch_bounds__(THREADS, 3)
void ssim_main(const float* __restrict__ pred, const float* __restrict__ gt,
               float* __restrict__ out)
{
    extern __shared__ unsigned char smem_raw[];
    SmemLayout& s = *reinterpret_cast<SmemLayout*>(smem_raw);

    const int tid  = threadIdx.x;
    const int warp = tid >> 5;
    const int lane = tid & 31;
    const float* pb = pred + (size_t)blockIdx.x * 12288;
    const float* gb = gt   + (size_t)blockIdx.x * 12288;

    // 6 distinct packed weights (Gaussian symmetry G[k] = G[10-k])
    u64 W6[6];
    #pragma unroll
    for (int k = 0; k < 6; ++k) W6[k] = pack2(G[k], G[k]);

    float local = 0.0f;

    for (int ch = 0; ch < 3; ++ch) {
        __syncthreads();

        // ---- load channel plane, pack (u,v) = (x+y, x-y) as bf16x2 --------
        for (int i = tid; i < 4096; i += THREADS) {
            const float x = pb[i * 3 + ch];
            const float y = gb[i * 3 + ch];
            s.plane[i >> 6][i & 63] = pk(x - y, x + y);   // hi=v, lo=u
        }
        __syncthreads();

        // ---- horizontal pass: seg=tid/64 (6 segs x 9 cols), r=tid%64 ------
        {
            const int seg = tid / 64;
            const int r   = tid & 63;
            const int c0  = seg * 9;

            // sweep 1: (u, v) -> hpq (stored raw, no cvt)
            {
                u64 acc[9];
                #pragma unroll
                for (int o = 0; o < 9; ++o) acc[o] = 0ull;
                #pragma unroll
                for (int j = 0; j < 19; ++j) {
                    const u64 uv = up2(s.plane[r][c0 + j]);
                    #pragma unroll
                    for (int k = 0; k < 11; ++k) {
                        const int o = j - k;             // compile-time pruned
                        if (o >= 0 && o < 9)
                            acc[o] = fma2(W6[k < 6 ? k : 10 - k], uv, acc[o]);
                    }
                }
                #pragma unroll
                for (int o = 0; o < 9; ++o) s.hpq[r][c0 + o] = acc[o];
            }
            // sweep 2: (u^2, v^2) -> hs
            {
                u64 acc[9];
                #pragma unroll
                for (int o = 0; o < 9; ++o) acc[o] = 0ull;
                #pragma unroll
                for (int j = 0; j < 19; ++j) {
                    const u64 uv = up2(s.plane[r][c0 + j]);
                    const u64 sq = mul2(uv, uv);
                    #pragma unroll
                    for (int k = 0; k < 11; ++k) {
                        const int o = j - k;
                        if (o >= 0 && o < 9)
                            acc[o] = fma2(W6[k < 6 ? k : 10 - k], sq, acc[o]);
                    }
                }
                #pragma unroll
                for (int o = 0; o < 9; ++o) s.hs[r][c0 + o] = acc[o];
            }
        }
        __syncthreads();

        // ---- vertical pass + ssim: 324 tasks = 6 row-segs x 54 cols -------
        if (tid < 324) {
            const int c  = tid % 54;
            const int r0 = (tid / 54) * 9;

            u64 apq[9];
            #pragma unroll
            for (int o = 0; o < 9; ++o) apq[o] = 0ull;
            #pragma unroll
            for (int j = 0; j < 19; ++j) {
                const u64 pq = s.hpq[r0 + j][c];         // LDS.64, no unpack
                #pragma unroll
                for (int k = 0; k < 11; ++k) {
                    const int o = j - k;
                    if (o >= 0 && o < 9)
                        apq[o] = fma2(W6[k < 6 ? k : 10 - k], pq, apq[o]);
                }
            }
            u64 asq[9];
            #pragma unroll
            for (int o = 0; o < 9; ++o) asq[o] = 0ull;
            #pragma unroll
            for (int j = 0; j < 19; ++j) {
                const u64 sq = s.hs[r0 + j][c];
                #pragma unroll
                for (int k = 0; k < 11; ++k) {
                    const int o = j - k;
                    if (o >= 0 && o < 9)
                        asq[o] = fma2(W6[k < 6 ? k : 10 - k], sq, asq[o]);
                }
            }
            #pragma unroll
            for (int o = 0; o < 9; ++o) {
                float p, q, su, sv;
                unpack2(apq[o], p, q);
                unpack2(asq[o], su, sv);
                const float P = p * p, Q = q * q;
                const float A = 0.5f * (P - Q);          // 2*mu1*mu2
                const float B = 0.5f * (P + Q);          // mu1^2 + mu2^2
                const float num = (A + C1) * (fmaf(0.5f, su - sv, C2) - A);
                const float den = (B + C1) * (fmaf(0.5f, su + sv, C2) - B);
                local += __fdividef(num, den);
            }
        }
    }

    // ---- fixed-order block reduction --------------------------------------
    __syncthreads();
    #pragma unroll
    for (int off = 16; off > 0; off >>= 1)
        local += __shfl_down_sync(0xffffffffu, local, off);
    if (lane == 0) s.red[warp] = local;
    __syncthreads();
    if (tid == 0) {
        float sum = 0.0f;
        #pragma unroll
        for (int w = 0; w < THREADS / 32; ++w) sum += s.red[w];
        g_part[blockIdx.x] = sum;
        __threadfence();
        s.ticket = atomicAdd(&g_count, 1u);
    }
    __syncthreads();

    // ---- last block: deterministic global reduction -----------------------
    if (s.ticket == NBLK - 1) {
        float sum = 0.0f;
        for (int i = tid; i < NBLK; i += THREADS) sum += g_part[i];
        #pragma unroll
        for (int off = 16; off > 0; off >>= 1)
            sum += __shfl_down_sync(0xffffffffu, sum, off);
        if (lane == 0) s.red[warp] = sum;
        __syncthreads();
        if (tid == 0) {
            float t = 0.0f;
            #pragma unroll
            for (int w = 0; w < THREADS / 32; ++w) t += s.red[w];
            out[0] = 1.0f - t * (1.0f / 17915904.0f);   // 2048*3*54*54
            g_count = 0;                                 // reset for replay
        }
    }
}

extern "C" void kernel_launch(void* const* d_in, const int* in_sizes, int n_in,
                              void* d_out, int out_size)
{
    const float* pred = (const float*)d_in[0];
    const float* gt   = (const float*)d_in[1];
    float* out        = (float*)d_out;

    cudaFuncSetAttribute(ssim_main, cudaFuncAttributeMaxDynamicSharedMemorySize,
                         SMEM_BYTES);
    ssim_main<<<NBLK, THREADS, SMEM_BYTES>>>(pred, gt, out);
}